// round 14
// baseline (speedup 1.0000x reference)
#include <cuda_runtime.h>
#include <cuda_fp16.h>
#include <math.h>
#include <stdint.h>

#define B_   8
#define CIN  64
#define COUT 32
#define HIN  128
#define WIN  128
#define HO   256
#define WO   256
#define ATT  16
#define KNUM 2
#define EPS  1e-5f
#define RATIO 0.49803921568627452f   // 127/255

typedef unsigned long long u64;
typedef unsigned int u32;

// Scratch device globals
__device__ float g_gap[B_ * CIN];                 // mean of upsampled x
// upsampled image, fp16, layout [b][g=ci/8][oy][ox][8ci] (uint4 per px-chunk)
__device__ __half g_xh[(size_t)B_ * CIN * HO * WO];
// folded per-sample weights, fp16, layout [b][q][co][ci]
__device__ __half g_w[B_ * 9 * COUT * CIN];
__device__ float g_bias[COUT];

// ---------------- warp-level MMA helpers (plain sm_103 PTX, sm_80+) --------
__device__ __forceinline__ u32 smem_to_u32(const void* p) {
    u32 a;
    asm("{ .reg .u64 t; cvta.to.shared.u64 t, %1; cvt.u32.u64 %0, t; }"
        : "=r"(a) : "l"(p));
    return a;
}
__device__ __forceinline__ void ldsm_x4(u32* r, u32 addr) {
    asm volatile("ldmatrix.sync.aligned.m8n8.x4.shared.b16 {%0,%1,%2,%3}, [%4];"
                 : "=r"(r[0]), "=r"(r[1]), "=r"(r[2]), "=r"(r[3]) : "r"(addr));
}
__device__ __forceinline__ void ldsm_x2(u32* r, u32 addr) {
    asm volatile("ldmatrix.sync.aligned.m8n8.x2.shared.b16 {%0,%1}, [%2];"
                 : "=r"(r[0]), "=r"(r[1]) : "r"(addr));
}
__device__ __forceinline__ void mma_fp16(float* c, const u32* a, const u32* b) {
    asm volatile(
        "mma.sync.aligned.m16n8k16.row.col.f32.f16.f16.f32 "
        "{%0,%1,%2,%3}, {%4,%5,%6,%7}, {%8,%9}, {%0,%1,%2,%3};"
        : "+f"(c[0]), "+f"(c[1]), "+f"(c[2]), "+f"(c[3])
        : "r"(a[0]), "r"(a[1]), "r"(a[2]), "r"(a[3]), "r"(b[0]), "r"(b[1]));
}

// ---------------------------------------------------------------------------
// K0: zero the GAP accumulator
// ---------------------------------------------------------------------------
__global__ void k_zero()
{
    g_gap[threadIdx.x] = 0.0f;
}

// ---------------------------------------------------------------------------
// K1: bilinear x2 upsample -> fp16 planes (two-phase: row-interp then col),
// with fused GAP (partials via dead sX smem, 1 warp per channel, 1 atomic).
// Block = (oy, g, b); thread = ox.
// ---------------------------------------------------------------------------
__global__ void __launch_bounds__(256) k_upsample(const float* __restrict__ x)
{
    __shared__ float sX[8][2][WIN];    // 8 KB; reused as sPart[8][256] later
    __shared__ float sRI[8][WIN];

    int oy = blockIdx.x;
    int g  = blockIdx.y;
    int b  = blockIdx.z;
    int ox = threadIdx.x;
    int lane = ox & 31;

    float py = (float)oy * RATIO;
    int   y0 = (int)py;
    float wy = py - (float)y0;
    int   y1 = min(y0 + 1, HIN - 1);

    const float* base = x + ((size_t)b * CIN + g * 8) * (HIN * WIN);
    for (int i = threadIdx.x; i < 8 * 2 * WIN; i += 256) {
        int k = i >> 8;
        int r = (i >> 7) & 1;
        int c = i & 127;
        sX[k][r][c] = __ldg(base + (size_t)k * (HIN * WIN) +
                            (r ? y1 : y0) * WIN + c);
    }
    __syncthreads();

    for (int i = threadIdx.x; i < 8 * WIN; i += 256) {
        int k = i >> 7, c = i & 127;
        sRI[k][c] = sX[k][0][c] * (1.0f - wy) + sX[k][1][c] * wy;
    }
    __syncthreads();   // sX dead after this point

    float px = (float)ox * RATIO;
    int   x0 = (int)px;
    float wx = px - (float)x0;
    int   x1 = min(x0 + 1, WIN - 1);

    float vals[8];
    #pragma unroll
    for (int k = 0; k < 8; k++)
        vals[k] = sRI[k][x0] * (1.0f - wx) + sRI[k][x1] * wx;

    u32 hw[4];
    #pragma unroll
    for (int j = 0; j < 4; j++) {
        u32 p = (u32)__half_as_ushort(__float2half(vals[2 * j]));
        p |= (u32)__half_as_ushort(__float2half(vals[2 * j + 1])) << 16;
        hw[j] = p;
    }
    ((uint4*)g_xh)[((size_t)(b * 8 + g) * HO + oy) * WO + ox] =
        make_uint4(hw[0], hw[1], hw[2], hw[3]);

    // fused GAP: stash partials in (dead) sX, one warp reduces one channel
    float* sPart = &sX[0][0][0];       // 8 * 256 floats
    #pragma unroll
    for (int k = 0; k < 8; k++)
        sPart[k * 256 + threadIdx.x] = vals[k];
    __syncthreads();

    int wq = threadIdx.x >> 5;         // warp id == channel within group
    float s = 0.0f;
    #pragma unroll
    for (int j = 0; j < 8; j++)
        s += sPart[wq * 256 + j * 32 + lane];
    #pragma unroll
    for (int off = 16; off > 0; off >>= 1)
        s += __shfl_xor_sync(0xFFFFFFFFu, s, off);
    if (lane == 0)
        atomicAdd(&g_gap[b * CIN + g * 8 + wq], s * (1.0f / (float)(HO * WO)));
}

// ---------------------------------------------------------------------------
// K2: attention MLP + weight fold -> fp16 weights [b][q][co][ci]
// ---------------------------------------------------------------------------
__global__ void k_attention(
    const float* __restrict__ fc_w,
    const float* __restrict__ bna_g, const float* __restrict__ bna_b,
    const float* __restrict__ bna_m, const float* __restrict__ bna_v,
    const float* __restrict__ ch_w,  const float* __restrict__ ch_b,
    const float* __restrict__ fil_w, const float* __restrict__ fil_b,
    const float* __restrict__ sp_w,  const float* __restrict__ sp_b,
    const float* __restrict__ k_w,   const float* __restrict__ k_b,
    const float* __restrict__ weight,
    const float* __restrict__ bn_g,  const float* __restrict__ bn_b,
    const float* __restrict__ bn_m,  const float* __restrict__ bn_v)
{
    int b = blockIdx.x;
    int t = threadIdx.x;
    __shared__ float sh[ATT];
    __shared__ float sch[CIN];
    __shared__ float sfs[COUT];
    __shared__ float ssp[9];
    __shared__ float sraw[KNUM];
    __shared__ float skk[KNUM];

    if (t < ATT) {
        const float* g = g_gap + b * CIN;
        float acc = 0.0f;
        #pragma unroll
        for (int ci = 0; ci < CIN; ci++) acc += fc_w[t * CIN + ci] * g[ci];
        acc = (acc - bna_m[t]) * rsqrtf(bna_v[t] + EPS) * bna_g[t] + bna_b[t];
        sh[t] = fmaxf(acc, 0.0f);
    }
    __syncthreads();
    if (t < CIN) {
        float a = ch_b[t];
        #pragma unroll
        for (int j = 0; j < ATT; j++) a += ch_w[t * ATT + j] * sh[j];
        sch[t] = 1.0f / (1.0f + expf(-a));
    } else if (t < CIN + COUT) {
        int co = t - CIN;
        float a = fil_b[co];
        #pragma unroll
        for (int j = 0; j < ATT; j++) a += fil_w[co * ATT + j] * sh[j];
        float fil = 1.0f / (1.0f + expf(-a));
        sfs[co] = fil * bn_g[co] * rsqrtf(bn_v[co] + EPS);
    } else if (t < CIN + COUT + 9) {
        int q = t - CIN - COUT;
        float a = sp_b[q];
        #pragma unroll
        for (int j = 0; j < ATT; j++) a += sp_w[q * ATT + j] * sh[j];
        ssp[q] = 1.0f / (1.0f + expf(-a));
    } else if (t < CIN + COUT + 9 + KNUM) {
        int k = t - CIN - COUT - 9;
        float a = k_b[k];
        #pragma unroll
        for (int j = 0; j < ATT; j++) a += k_w[k * ATT + j] * sh[j];
        sraw[k] = a;
    }
    __syncthreads();
    if (t == 0) {
        float m  = fmaxf(sraw[0], sraw[1]);
        float e0 = expf(sraw[0] - m);
        float e1 = expf(sraw[1] - m);
        float inv = 1.0f / (e0 + e1);
        skk[0] = e0 * inv;
        skk[1] = e1 * inv;
    }
    __syncthreads();

    const int WSZ = COUT * CIN * 9;
    for (int idx = t; idx < WSZ; idx += blockDim.x) {
        int co  = idx / (CIN * 9);
        int rem = idx % (CIN * 9);
        int ci  = rem / 9;
        int q   = rem % 9;
        float w = skk[0] * weight[idx] + skk[1] * weight[WSZ + idx];
        w = w * ssp[q] * sch[ci] * sfs[co];
        g_w[(((size_t)b * 9 + q) * COUT + co) * CIN + ci] = __float2half(w);
    }
    if (b == 0 && t < COUT)
        g_bias[t] = bn_b[t] - bn_m[t] * bn_g[t] * rsqrtf(bn_v[t] + EPS);
}

// ---------------------------------------------------------------------------
// K3: implicit-GEMM conv, split-k across warp pairs (proven R13 mainloop).
// New epilogue: both k-halves combine in a buf[co][px] fp32 smem buffer
// (stride 136), then ALL 256 threads do bias+GELU on 16 px each with
// LDS.128 / STG.128 fully coalesced.
// ---------------------------------------------------------------------------
#define AROWB 8448            // 66 * 128 bytes
#define OFF_B 0               // 9 * 4096 = 36864
#define OFF_A 36864
#define SMEM_TOTAL (OFF_A + 4 * AROWB)   // 70656
#define BUFSTRIDE 136

#define SWZC(byte, r) ((byte) ^ (((r) & 7) << 4))

__global__ void __launch_bounds__(256, 3)
k_conv(float* __restrict__ out)
{
    extern __shared__ char smem[];
    u32 sb = smem_to_u32(smem);
    int tid  = threadIdx.x;
    int w    = tid >> 5;
    int lane = tid & 31;
    int b    = blockIdx.z;
    int r0   = blockIdx.y * 2;
    int c0   = blockIdx.x * 64;

    int kh   = w >> 2;            // k-half (0: ci 0-31, 1: ci 32-63)
    int pg   = w & 3;             // pixel group
    int wrow = pg >> 1;           // row within tile (0..1)
    int wcol = (pg & 1) * 32;     // col base within 64-tile

    // ---- fill B: 9 q x 32 n x 8 chunks ------------------------------------
    for (int i = tid; i < 2304; i += 256) {
        int q    = i / 256;
        int rem2 = i % 256;
        int n    = rem2 >> 3;
        int g    = rem2 & 7;
        uint4 v = *(const uint4*)(g_w +
            (((size_t)b * 9 + q) * COUT + n) * CIN + g * 8);
        *(uint4*)(smem + OFF_B + q * 4096 + n * 128 + SWZC(g * 16, n)) = v;
    }

    // ---- fill A from g_xh: 4 rows x 8 chunks x 66 px ----------------------
    const uint4* xh4 = (const uint4*)g_xh;
    for (int i = tid; i < 4 * 8 * 66; i += 256) {
        int row = i / (8 * 66);
        int rem = i % (8 * 66);
        int g   = rem / 66;
        int p   = rem % 66;
        int oy  = r0 - 1 + row;
        int oc  = c0 - 1 + p;
        uint4 v = make_uint4(0, 0, 0, 0);
        if ((unsigned)oy < (unsigned)HO && (unsigned)oc < (unsigned)WO)
            v = xh4[((size_t)(b * 8 + g) * HO + oy) * WO + oc];
        *(uint4*)(smem + OFF_A + row * AROWB + p * 128 + SWZC(g * 16, p)) = v;
    }
    __syncthreads();

    // ---- mainloop: 9 taps x 2 k-steps (this warp's half) ------------------
    float acc[2][4][4];
    #pragma unroll
    for (int mt = 0; mt < 2; mt++)
        #pragma unroll
        for (int nt = 0; nt < 4; nt++)
            #pragma unroll
            for (int r = 0; r < 4; r++) acc[mt][nt][r] = 0.0f;

    #pragma unroll 1
    for (int q = 0; q < 9; q++) {
        int ky = q / 3, kx = q % 3;
        u32 arow  = sb + OFF_A + (wrow + ky) * AROWB;
        u32 bbase = sb + OFF_B + q * 4096;
        #pragma unroll
        for (int ks = 0; ks < 2; ks++) {
            int kb = (kh * 2 + ks) * 32;      // 16 fp16 = 32 bytes
            u32 bfr[4][2];
            #pragma unroll
            for (int nt = 0; nt < 4; nt++) {
                int n = nt * 8 + (lane & 7);
                u32 addr = bbase + n * 128 +
                           SWZC(kb + ((lane >> 3) & 1) * 16, n);
                ldsm_x2(bfr[nt], addr);
            }
            #pragma unroll
            for (int mt = 0; mt < 2; mt++) {
                int p = wcol + mt * 16 + (lane & 15) + kx;
                u32 addr = arow + p * 128 +
                           SWZC(kb + ((lane >> 4) ? 16 : 0), p);
                u32 afr[4];
                ldsm_x4(afr, addr);
                #pragma unroll
                for (int nt = 0; nt < 4; nt++)
                    mma_fp16(acc[mt][nt], afr, bfr[nt]);
            }
        }
    }

    // ---- combine k-halves in smem buf[co][px] (B region is dead) ----------
    float* buf = (float*)(smem + OFF_B);   // 32 * 136 * 4 = 17408 B
    int pxbase = wrow * 64 + wcol;
    __syncthreads();
    if (kh == 0) {
        #pragma unroll
        for (int mt = 0; mt < 2; mt++)
            #pragma unroll
            for (int nt = 0; nt < 4; nt++)
                #pragma unroll
                for (int r = 0; r < 4; r++) {
                    int px = pxbase + mt * 16 + (lane >> 2) + 8 * (r >> 1);
                    int co = nt * 8 + (lane & 3) * 2 + (r & 1);
                    buf[co * BUFSTRIDE + px] = acc[mt][nt][r];
                }
    }
    __syncthreads();
    if (kh == 1) {
        #pragma unroll
        for (int mt = 0; mt < 2; mt++)
            #pragma unroll
            for (int nt = 0; nt < 4; nt++)
                #pragma unroll
                for (int r = 0; r < 4; r++) {
                    int px = pxbase + mt * 16 + (lane >> 2) + 8 * (r >> 1);
                    int co = nt * 8 + (lane & 3) * 2 + (r & 1);
                    buf[co * BUFSTRIDE + px] += acc[mt][nt][r];
                }
    }
    __syncthreads();

    // ---- epilogue: all 256 threads, 16 consecutive px of one cout ---------
    {
        int co  = tid >> 3;
        int grp = tid & 7;              // px group: 16 px each
        float bias = g_bias[co];
        const float4* bp = (const float4*)(buf + co * BUFSTRIDE + grp * 16);
        int row = r0 + (grp >> 2);
        int col = c0 + (grp & 3) * 16;
        float* op = out + (((size_t)b * COUT + co) * HO + row) * WO + col;
        #pragma unroll
        for (int v4 = 0; v4 < 4; v4++) {
            float4 d = bp[v4];
            d.x += bias; d.y += bias; d.z += bias; d.w += bias;
            d.x = 0.5f * d.x * (1.0f + erff(d.x * 0.70710678118654752f));
            d.y = 0.5f * d.y * (1.0f + erff(d.y * 0.70710678118654752f));
            d.z = 0.5f * d.z * (1.0f + erff(d.z * 0.70710678118654752f));
            d.w = 0.5f * d.w * (1.0f + erff(d.w * 0.70710678118654752f));
            *(float4*)(op + v4 * 4) = d;
        }
    }
}

// ---------------------------------------------------------------------------
extern "C" void kernel_launch(void* const* d_in, const int* in_sizes, int n_in,
                              void* d_out, int out_size)
{
    const float* x      = (const float*)d_in[0];
    const float* fc_w   = (const float*)d_in[1];
    const float* bna_g  = (const float*)d_in[2];
    const float* bna_b  = (const float*)d_in[3];
    const float* bna_m  = (const float*)d_in[4];
    const float* bna_v  = (const float*)d_in[5];
    const float* ch_w   = (const float*)d_in[6];
    const float* ch_b   = (const float*)d_in[7];
    const float* fil_w  = (const float*)d_in[8];
    const float* fil_b  = (const float*)d_in[9];
    const float* sp_w   = (const float*)d_in[10];
    const float* sp_b   = (const float*)d_in[11];
    const float* k_w    = (const float*)d_in[12];
    const float* k_b    = (const float*)d_in[13];
    const float* weight = (const float*)d_in[14];
    const float* bn_g   = (const float*)d_in[15];
    const float* bn_b   = (const float*)d_in[16];
    const float* bn_m   = (const float*)d_in[17];
    const float* bn_v   = (const float*)d_in[18];

    cudaFuncSetAttribute(k_conv, cudaFuncAttributeMaxDynamicSharedMemorySize,
                         SMEM_TOTAL);

    k_zero<<<1, B_ * CIN>>>();
    k_upsample<<<dim3(HO, 8, B_), 256>>>(x);
    k_attention<<<B_, 256>>>(fc_w, bna_g, bna_b, bna_m, bna_v,
                             ch_w, ch_b, fil_w, fil_b, sp_w, sp_b, k_w, k_b,
                             weight, bn_g, bn_b, bn_m, bn_v);
    k_conv<<<dim3(WO / 64, HO / 2, B_), 256, SMEM_TOTAL>>>((float*)d_out);
}

// round 15
// speedup vs baseline: 1.2113x; 1.2113x over previous
#include <cuda_runtime.h>
#include <cuda_fp16.h>
#include <math.h>
#include <stdint.h>

#define B_   8
#define CIN  64
#define COUT 32
#define HIN  128
#define WIN  128
#define HO   256
#define WO   256
#define ATT  16
#define KNUM 2
#define EPS  1e-5f
#define RATIO 0.49803921568627452f   // 127/255

typedef unsigned long long u64;
typedef unsigned int u32;

// Scratch device globals
__device__ float g_gap[B_ * CIN];                 // mean of upsampled x
// upsampled image, fp16, layout [b][g=ci/8][oy][ox][8ci] (uint4 per px-chunk)
__device__ __half g_xh[(size_t)B_ * CIN * HO * WO];
// folded per-sample weights, fp16, layout [b][q][co][ci]
__device__ __half g_w[B_ * 9 * COUT * CIN];
__device__ float g_bias[COUT];

// ---------------- warp-level MMA helpers (plain sm_103 PTX, sm_80+) --------
__device__ __forceinline__ u32 smem_to_u32(const void* p) {
    u32 a;
    asm("{ .reg .u64 t; cvta.to.shared.u64 t, %1; cvt.u32.u64 %0, t; }"
        : "=r"(a) : "l"(p));
    return a;
}
__device__ __forceinline__ void ldsm_x4(u32* r, u32 addr) {
    asm volatile("ldmatrix.sync.aligned.m8n8.x4.shared.b16 {%0,%1,%2,%3}, [%4];"
                 : "=r"(r[0]), "=r"(r[1]), "=r"(r[2]), "=r"(r[3]) : "r"(addr));
}
__device__ __forceinline__ void ldsm_x2(u32* r, u32 addr) {
    asm volatile("ldmatrix.sync.aligned.m8n8.x2.shared.b16 {%0,%1}, [%2];"
                 : "=r"(r[0]), "=r"(r[1]) : "r"(addr));
}
__device__ __forceinline__ void mma_fp16(float* c, const u32* a, const u32* b) {
    asm volatile(
        "mma.sync.aligned.m16n8k16.row.col.f32.f16.f16.f32 "
        "{%0,%1,%2,%3}, {%4,%5,%6,%7}, {%8,%9}, {%0,%1,%2,%3};"
        : "+f"(c[0]), "+f"(c[1]), "+f"(c[2]), "+f"(c[3])
        : "r"(a[0]), "r"(a[1]), "r"(a[2]), "r"(a[3]), "r"(b[0]), "r"(b[1]));
}

// ---------------------------------------------------------------------------
// K_gap: GAP of the virtual upsample via separable row weights R
// ---------------------------------------------------------------------------
__global__ void k_gap(const float* __restrict__ x)
{
    __shared__ float sR[HIN];
    __shared__ float red[256];
    int t = threadIdx.x;
    if (t < HIN) sR[t] = 0.0f;
    __syncthreads();
    if (t < HO) {
        float py = (float)t * RATIO;
        int   y0 = (int)py;
        float wy = py - (float)y0;
        int   y1 = min(y0 + 1, HIN - 1);
        atomicAdd(&sR[y0], 1.0f - wy);
        atomicAdd(&sR[y1], wy);
    }
    __syncthreads();
    int bc = blockIdx.x;
    const float* __restrict__ plane = x + (size_t)bc * HIN * WIN;
    float lsum = 0.0f;
    for (int idx = t; idx < HIN * WIN; idx += 256) {
        int y = idx >> 7, c = idx & 127;
        lsum += plane[idx] * sR[y] * sR[c];
    }
    red[t] = lsum;
    __syncthreads();
    for (int s = 128; s > 0; s >>= 1) {
        if (t < s) red[t] += red[t + s];
        __syncthreads();
    }
    if (t == 0) g_gap[bc] = red[0] * (1.0f / (float)(HO * WO));
}

// ---------------------------------------------------------------------------
// K1: bilinear x2 upsample -> fp16 planes (two-phase: row-interp then col)
// ---------------------------------------------------------------------------
__global__ void __launch_bounds__(256) k_upsample(const float* __restrict__ x)
{
    __shared__ float sX[8][2][WIN];
    __shared__ float sRI[8][WIN];

    int oy = blockIdx.x;
    int g  = blockIdx.y;
    int b  = blockIdx.z;
    int ox = threadIdx.x;

    float py = (float)oy * RATIO;
    int   y0 = (int)py;
    float wy = py - (float)y0;
    int   y1 = min(y0 + 1, HIN - 1);

    const float* base = x + ((size_t)b * CIN + g * 8) * (HIN * WIN);
    for (int i = threadIdx.x; i < 8 * 2 * WIN; i += 256) {
        int k = i >> 8;
        int r = (i >> 7) & 1;
        int c = i & 127;
        sX[k][r][c] = __ldg(base + (size_t)k * (HIN * WIN) +
                            (r ? y1 : y0) * WIN + c);
    }
    __syncthreads();

    for (int i = threadIdx.x; i < 8 * WIN; i += 256) {
        int k = i >> 7, c = i & 127;
        sRI[k][c] = sX[k][0][c] * (1.0f - wy) + sX[k][1][c] * wy;
    }
    __syncthreads();

    float px = (float)ox * RATIO;
    int   x0 = (int)px;
    float wx = px - (float)x0;
    int   x1 = min(x0 + 1, WIN - 1);

    u32 hw[4];
    #pragma unroll
    for (int j = 0; j < 4; j++) {
        int k0 = 2 * j, k1 = 2 * j + 1;
        float va = sRI[k0][x0] * (1.0f - wx) + sRI[k0][x1] * wx;
        float vb = sRI[k1][x0] * (1.0f - wx) + sRI[k1][x1] * wx;
        u32 p = (u32)__half_as_ushort(__float2half(va));
        p |= (u32)__half_as_ushort(__float2half(vb)) << 16;
        hw[j] = p;
    }
    ((uint4*)g_xh)[((size_t)(b * 8 + g) * HO + oy) * WO + ox] =
        make_uint4(hw[0], hw[1], hw[2], hw[3]);
}

// ---------------------------------------------------------------------------
// K2: attention MLP + weight fold -> fp16 weights [b][q][co][ci]
// ---------------------------------------------------------------------------
__global__ void k_attention(
    const float* __restrict__ fc_w,
    const float* __restrict__ bna_g, const float* __restrict__ bna_b,
    const float* __restrict__ bna_m, const float* __restrict__ bna_v,
    const float* __restrict__ ch_w,  const float* __restrict__ ch_b,
    const float* __restrict__ fil_w, const float* __restrict__ fil_b,
    const float* __restrict__ sp_w,  const float* __restrict__ sp_b,
    const float* __restrict__ k_w,   const float* __restrict__ k_b,
    const float* __restrict__ weight,
    const float* __restrict__ bn_g,  const float* __restrict__ bn_b,
    const float* __restrict__ bn_m,  const float* __restrict__ bn_v)
{
    int b = blockIdx.x;
    int t = threadIdx.x;
    __shared__ float sh[ATT];
    __shared__ float sch[CIN];
    __shared__ float sfs[COUT];
    __shared__ float ssp[9];
    __shared__ float sraw[KNUM];
    __shared__ float skk[KNUM];

    if (t < ATT) {
        const float* g = g_gap + b * CIN;
        float acc = 0.0f;
        #pragma unroll
        for (int ci = 0; ci < CIN; ci++) acc += fc_w[t * CIN + ci] * g[ci];
        acc = (acc - bna_m[t]) * rsqrtf(bna_v[t] + EPS) * bna_g[t] + bna_b[t];
        sh[t] = fmaxf(acc, 0.0f);
    }
    __syncthreads();
    if (t < CIN) {
        float a = ch_b[t];
        #pragma unroll
        for (int j = 0; j < ATT; j++) a += ch_w[t * ATT + j] * sh[j];
        sch[t] = 1.0f / (1.0f + expf(-a));
    } else if (t < CIN + COUT) {
        int co = t - CIN;
        float a = fil_b[co];
        #pragma unroll
        for (int j = 0; j < ATT; j++) a += fil_w[co * ATT + j] * sh[j];
        float fil = 1.0f / (1.0f + expf(-a));
        sfs[co] = fil * bn_g[co] * rsqrtf(bn_v[co] + EPS);
    } else if (t < CIN + COUT + 9) {
        int q = t - CIN - COUT;
        float a = sp_b[q];
        #pragma unroll
        for (int j = 0; j < ATT; j++) a += sp_w[q * ATT + j] * sh[j];
        ssp[q] = 1.0f / (1.0f + expf(-a));
    } else if (t < CIN + COUT + 9 + KNUM) {
        int k = t - CIN - COUT - 9;
        float a = k_b[k];
        #pragma unroll
        for (int j = 0; j < ATT; j++) a += k_w[k * ATT + j] * sh[j];
        sraw[k] = a;
    }
    __syncthreads();
    if (t == 0) {
        float m  = fmaxf(sraw[0], sraw[1]);
        float e0 = expf(sraw[0] - m);
        float e1 = expf(sraw[1] - m);
        float inv = 1.0f / (e0 + e1);
        skk[0] = e0 * inv;
        skk[1] = e1 * inv;
    }
    __syncthreads();

    const int WSZ = COUT * CIN * 9;
    for (int idx = t; idx < WSZ; idx += blockDim.x) {
        int co  = idx / (CIN * 9);
        int rem = idx % (CIN * 9);
        int ci  = rem / 9;
        int q   = rem % 9;
        float w = skk[0] * weight[idx] + skk[1] * weight[WSZ + idx];
        w = w * ssp[q] * sch[ci] * sfs[co];
        g_w[(((size_t)b * 9 + q) * COUT + co) * CIN + ci] = __float2half(w);
    }
    if (b == 0 && t < COUT)
        g_bias[t] = bn_b[t] - bn_m[t] * bn_g[t] * rsqrtf(bn_v[t] + EPS);
}

// ---------------------------------------------------------------------------
// K3: implicit-GEMM conv, split-k across warp pairs (R13 structure).
// ILP fix: batch all 12 LDSM ops of a q-iteration before the 32 MMAs
// (bfr[2][4][2] + afr[2][2][4]) so LDS latency overlaps.
// ---------------------------------------------------------------------------
#define AROWB 8448            // 66 * 128 bytes
#define OFF_B 0               // 9 * 4096 = 36864
#define OFF_A 36864
#define SMEM_TOTAL (OFF_A + 4 * AROWB)   // 70656

#define SWZC(byte, r) ((byte) ^ (((r) & 7) << 4))

__global__ void __launch_bounds__(256, 3)
k_conv(float* __restrict__ out)
{
    extern __shared__ char smem[];
    u32 sb = smem_to_u32(smem);
    int tid  = threadIdx.x;
    int w    = tid >> 5;
    int lane = tid & 31;
    int b    = blockIdx.z;
    int r0   = blockIdx.y * 2;
    int c0   = blockIdx.x * 64;

    int kh   = w >> 2;            // k-half (0: ci 0-31, 1: ci 32-63)
    int pg   = w & 3;             // pixel group
    int wrow = pg >> 1;           // row within tile (0..1)
    int wcol = (pg & 1) * 32;     // col base within 64-tile

    // ---- fill B: 9 q x 32 n x 8 chunks ------------------------------------
    for (int i = tid; i < 2304; i += 256) {
        int q    = i / 256;
        int rem2 = i % 256;
        int n    = rem2 >> 3;
        int g    = rem2 & 7;
        uint4 v = *(const uint4*)(g_w +
            (((size_t)b * 9 + q) * COUT + n) * CIN + g * 8);
        *(uint4*)(smem + OFF_B + q * 4096 + n * 128 + SWZC(g * 16, n)) = v;
    }

    // ---- fill A from g_xh: 4 rows x 8 chunks x 66 px ----------------------
    const uint4* xh4 = (const uint4*)g_xh;
    for (int i = tid; i < 4 * 8 * 66; i += 256) {
        int row = i / (8 * 66);
        int rem = i % (8 * 66);
        int g   = rem / 66;
        int p   = rem % 66;
        int oy  = r0 - 1 + row;
        int oc  = c0 - 1 + p;
        uint4 v = make_uint4(0, 0, 0, 0);
        if ((unsigned)oy < (unsigned)HO && (unsigned)oc < (unsigned)WO)
            v = xh4[((size_t)(b * 8 + g) * HO + oy) * WO + oc];
        *(uint4*)(smem + OFF_A + row * AROWB + p * 128 + SWZC(g * 16, p)) = v;
    }
    __syncthreads();

    // ---- mainloop: 9 taps; all 12 LDSMs batched, then 32 MMAs -------------
    float acc[2][4][4];
    #pragma unroll
    for (int mt = 0; mt < 2; mt++)
        #pragma unroll
        for (int nt = 0; nt < 4; nt++)
            #pragma unroll
            for (int r = 0; r < 4; r++) acc[mt][nt][r] = 0.0f;

    #pragma unroll 1
    for (int q = 0; q < 9; q++) {
        int ky = q / 3, kx = q % 3;
        u32 arow  = sb + OFF_A + (wrow + ky) * AROWB;
        u32 bbase = sb + OFF_B + q * 4096;

        u32 bfr[2][4][2];
        u32 afr[2][2][4];
        #pragma unroll
        for (int ks = 0; ks < 2; ks++) {
            int kb = (kh * 2 + ks) * 32;      // 16 fp16 = 32 bytes
            #pragma unroll
            for (int nt = 0; nt < 4; nt++) {
                int n = nt * 8 + (lane & 7);
                ldsm_x2(bfr[ks][nt], bbase + n * 128 +
                        SWZC(kb + ((lane >> 3) & 1) * 16, n));
            }
        }
        #pragma unroll
        for (int ks = 0; ks < 2; ks++) {
            int kb = (kh * 2 + ks) * 32;
            #pragma unroll
            for (int mt = 0; mt < 2; mt++) {
                int p = wcol + mt * 16 + (lane & 15) + kx;
                ldsm_x4(afr[ks][mt], arow + p * 128 +
                        SWZC(kb + ((lane >> 4) ? 16 : 0), p));
            }
        }
        #pragma unroll
        for (int ks = 0; ks < 2; ks++)
            #pragma unroll
            for (int mt = 0; mt < 2; mt++)
                #pragma unroll
                for (int nt = 0; nt < 4; nt++)
                    mma_fp16(acc[mt][nt], afr[ks][mt], bfr[ks][nt]);
    }

    // ---- cross-k reduction through smem (B region is dead now) ------------
    float* buf = (float*)(smem + OFF_B);
    __syncthreads();
    if (kh == 1) {
        #pragma unroll
        for (int mt = 0; mt < 2; mt++)
            #pragma unroll
            for (int nt = 0; nt < 4; nt++)
                #pragma unroll
                for (int r = 0; r < 4; r++)
                    buf[((((pg * 2 + mt) * 4 + nt) * 4 + r) * 32) + lane] =
                        acc[mt][nt][r];
    }
    __syncthreads();

    // ---- epilogue (kh==0 warps): add partner half, bias + exact GELU ------
    if (kh == 0) {
        int row = r0 + wrow;
        #pragma unroll
        for (int mt = 0; mt < 2; mt++) {
            int colb = c0 + wcol + mt * 16 + (lane >> 2);
            #pragma unroll
            for (int nt = 0; nt < 4; nt++) {
                int co0 = nt * 8 + (lane & 3) * 2;
                float b0 = g_bias[co0];
                float b1 = g_bias[co0 + 1];
                #pragma unroll
                for (int r = 0; r < 4; r++) {
                    float v = acc[mt][nt][r] +
                        buf[((((pg * 2 + mt) * 4 + nt) * 4 + r) * 32) + lane];
                    int co = co0 + (r & 1);
                    int cc = colb + ((r >> 1) ? 8 : 0);
                    v += (r & 1) ? b1 : b0;
                    out[(((size_t)b * COUT + co) * HO + row) * WO + cc] =
                        0.5f * v * (1.0f + erff(v * 0.70710678118654752f));
                }
            }
        }
    }
}

// ---------------------------------------------------------------------------
extern "C" void kernel_launch(void* const* d_in, const int* in_sizes, int n_in,
                              void* d_out, int out_size)
{
    const float* x      = (const float*)d_in[0];
    const float* fc_w   = (const float*)d_in[1];
    const float* bna_g  = (const float*)d_in[2];
    const float* bna_b  = (const float*)d_in[3];
    const float* bna_m  = (const float*)d_in[4];
    const float* bna_v  = (const float*)d_in[5];
    const float* ch_w   = (const float*)d_in[6];
    const float* ch_b   = (const float*)d_in[7];
    const float* fil_w  = (const float*)d_in[8];
    const float* fil_b  = (const float*)d_in[9];
    const float* sp_w   = (const float*)d_in[10];
    const float* sp_b   = (const float*)d_in[11];
    const float* k_w    = (const float*)d_in[12];
    const float* k_b    = (const float*)d_in[13];
    const float* weight = (const float*)d_in[14];
    const float* bn_g   = (const float*)d_in[15];
    const float* bn_b   = (const float*)d_in[16];
    const float* bn_m   = (const float*)d_in[17];
    const float* bn_v   = (const float*)d_in[18];

    cudaFuncSetAttribute(k_conv, cudaFuncAttributeMaxDynamicSharedMemorySize,
                         SMEM_TOTAL);

    k_gap<<<B_ * CIN, 256>>>(x);
    k_upsample<<<dim3(HO, 8, B_), 256>>>(x);
    k_attention<<<B_, 256>>>(fc_w, bna_g, bna_b, bna_m, bna_v,
                             ch_w, ch_b, fil_w, fil_b, sp_w, sp_b, k_w, k_b,
                             weight, bn_g, bn_b, bn_m, bn_v);
    k_conv<<<dim3(WO / 64, HO / 2, B_), 256, SMEM_TOTAL>>>((float*)d_out);
}

// round 16
// speedup vs baseline: 1.2673x; 1.0463x over previous
#include <cuda_runtime.h>
#include <cuda_fp16.h>
#include <math.h>
#include <stdint.h>

#define B_   8
#define CIN  64
#define COUT 32
#define HIN  128
#define WIN  128
#define HO   256
#define WO   256
#define ATT  16
#define KNUM 2
#define EPS  1e-5f
#define RATIO 0.49803921568627452f   // 127/255

typedef unsigned long long u64;
typedef unsigned int u32;

// Scratch device globals
__device__ float g_gap[B_ * CIN];                 // mean of upsampled x
// upsampled image, fp16, layout [b][g=ci/8][oy][ox][8ci] (uint4 per px-chunk)
__device__ __half g_xh[(size_t)B_ * CIN * HO * WO];
// folded per-sample weights, fp16, layout [b][q][co][ci]
__device__ __half g_w[B_ * 9 * COUT * CIN];
__device__ float g_bias[COUT];

// ---------------- warp-level MMA helpers (plain sm_103 PTX, sm_80+) --------
__device__ __forceinline__ u32 smem_to_u32(const void* p) {
    u32 a;
    asm("{ .reg .u64 t; cvta.to.shared.u64 t, %1; cvt.u32.u64 %0, t; }"
        : "=r"(a) : "l"(p));
    return a;
}
__device__ __forceinline__ void ldsm_x4(u32* r, u32 addr) {
    asm volatile("ldmatrix.sync.aligned.m8n8.x4.shared.b16 {%0,%1,%2,%3}, [%4];"
                 : "=r"(r[0]), "=r"(r[1]), "=r"(r[2]), "=r"(r[3]) : "r"(addr));
}
__device__ __forceinline__ void ldsm_x2(u32* r, u32 addr) {
    asm volatile("ldmatrix.sync.aligned.m8n8.x2.shared.b16 {%0,%1}, [%2];"
                 : "=r"(r[0]), "=r"(r[1]) : "r"(addr));
}
__device__ __forceinline__ void mma_fp16(float* c, const u32* a, const u32* b) {
    asm volatile(
        "mma.sync.aligned.m16n8k16.row.col.f32.f16.f16.f32 "
        "{%0,%1,%2,%3}, {%4,%5,%6,%7}, {%8,%9}, {%0,%1,%2,%3};"
        : "+f"(c[0]), "+f"(c[1]), "+f"(c[2]), "+f"(c[3])
        : "r"(a[0]), "r"(a[1]), "r"(a[2]), "r"(a[3]), "r"(b[0]), "r"(b[1]));
}
__device__ __forceinline__ void cp16(u32 saddr, const void* gaddr, u32 srcsz) {
    asm volatile("cp.async.cg.shared.global [%0], [%1], 16, %2;"
                 :: "r"(saddr), "l"(gaddr), "r"(srcsz));
}

// ---------------------------------------------------------------------------
// K_gap: GAP of the virtual upsample via separable row weights R
// ---------------------------------------------------------------------------
__global__ void k_gap(const float* __restrict__ x)
{
    __shared__ float sR[HIN];
    __shared__ float red[256];
    int t = threadIdx.x;
    if (t < HIN) sR[t] = 0.0f;
    __syncthreads();
    if (t < HO) {
        float py = (float)t * RATIO;
        int   y0 = (int)py;
        float wy = py - (float)y0;
        int   y1 = min(y0 + 1, HIN - 1);
        atomicAdd(&sR[y0], 1.0f - wy);
        atomicAdd(&sR[y1], wy);
    }
    __syncthreads();
    int bc = blockIdx.x;
    const float* __restrict__ plane = x + (size_t)bc * HIN * WIN;
    float lsum = 0.0f;
    for (int idx = t; idx < HIN * WIN; idx += 256) {
        int y = idx >> 7, c = idx & 127;
        lsum += plane[idx] * sR[y] * sR[c];
    }
    red[t] = lsum;
    __syncthreads();
    for (int s = 128; s > 0; s >>= 1) {
        if (t < s) red[t] += red[t + s];
        __syncthreads();
    }
    if (t == 0) g_gap[bc] = red[0] * (1.0f / (float)(HO * WO));
}

// ---------------------------------------------------------------------------
// K1: bilinear x2 upsample -> fp16 planes (two-phase: row-interp then col)
// ---------------------------------------------------------------------------
__global__ void __launch_bounds__(256) k_upsample(const float* __restrict__ x)
{
    __shared__ float sX[8][2][WIN];
    __shared__ float sRI[8][WIN];

    int oy = blockIdx.x;
    int g  = blockIdx.y;
    int b  = blockIdx.z;
    int ox = threadIdx.x;

    float py = (float)oy * RATIO;
    int   y0 = (int)py;
    float wy = py - (float)y0;
    int   y1 = min(y0 + 1, HIN - 1);

    const float* base = x + ((size_t)b * CIN + g * 8) * (HIN * WIN);
    for (int i = threadIdx.x; i < 8 * 2 * WIN; i += 256) {
        int k = i >> 8;
        int r = (i >> 7) & 1;
        int c = i & 127;
        sX[k][r][c] = __ldg(base + (size_t)k * (HIN * WIN) +
                            (r ? y1 : y0) * WIN + c);
    }
    __syncthreads();

    for (int i = threadIdx.x; i < 8 * WIN; i += 256) {
        int k = i >> 7, c = i & 127;
        sRI[k][c] = sX[k][0][c] * (1.0f - wy) + sX[k][1][c] * wy;
    }
    __syncthreads();

    float px = (float)ox * RATIO;
    int   x0 = (int)px;
    float wx = px - (float)x0;
    int   x1 = min(x0 + 1, WIN - 1);

    u32 hw[4];
    #pragma unroll
    for (int j = 0; j < 4; j++) {
        int k0 = 2 * j, k1 = 2 * j + 1;
        float va = sRI[k0][x0] * (1.0f - wx) + sRI[k0][x1] * wx;
        float vb = sRI[k1][x0] * (1.0f - wx) + sRI[k1][x1] * wx;
        u32 p = (u32)__half_as_ushort(__float2half(va));
        p |= (u32)__half_as_ushort(__float2half(vb)) << 16;
        hw[j] = p;
    }
    ((uint4*)g_xh)[((size_t)(b * 8 + g) * HO + oy) * WO + ox] =
        make_uint4(hw[0], hw[1], hw[2], hw[3]);
}

// ---------------------------------------------------------------------------
// K2: attention MLP + weight fold -> fp16 weights [b][q][co][ci]
// ---------------------------------------------------------------------------
__global__ void k_attention(
    const float* __restrict__ fc_w,
    const float* __restrict__ bna_g, const float* __restrict__ bna_b,
    const float* __restrict__ bna_m, const float* __restrict__ bna_v,
    const float* __restrict__ ch_w,  const float* __restrict__ ch_b,
    const float* __restrict__ fil_w, const float* __restrict__ fil_b,
    const float* __restrict__ sp_w,  const float* __restrict__ sp_b,
    const float* __restrict__ k_w,   const float* __restrict__ k_b,
    const float* __restrict__ weight,
    const float* __restrict__ bn_g,  const float* __restrict__ bn_b,
    const float* __restrict__ bn_m,  const float* __restrict__ bn_v)
{
    int b = blockIdx.x;
    int t = threadIdx.x;
    __shared__ float sh[ATT];
    __shared__ float sch[CIN];
    __shared__ float sfs[COUT];
    __shared__ float ssp[9];
    __shared__ float sraw[KNUM];
    __shared__ float skk[KNUM];

    if (t < ATT) {
        const float* g = g_gap + b * CIN;
        float acc = 0.0f;
        #pragma unroll
        for (int ci = 0; ci < CIN; ci++) acc += fc_w[t * CIN + ci] * g[ci];
        acc = (acc - bna_m[t]) * rsqrtf(bna_v[t] + EPS) * bna_g[t] + bna_b[t];
        sh[t] = fmaxf(acc, 0.0f);
    }
    __syncthreads();
    if (t < CIN) {
        float a = ch_b[t];
        #pragma unroll
        for (int j = 0; j < ATT; j++) a += ch_w[t * ATT + j] * sh[j];
        sch[t] = 1.0f / (1.0f + expf(-a));
    } else if (t < CIN + COUT) {
        int co = t - CIN;
        float a = fil_b[co];
        #pragma unroll
        for (int j = 0; j < ATT; j++) a += fil_w[co * ATT + j] * sh[j];
        float fil = 1.0f / (1.0f + expf(-a));
        sfs[co] = fil * bn_g[co] * rsqrtf(bn_v[co] + EPS);
    } else if (t < CIN + COUT + 9) {
        int q = t - CIN - COUT;
        float a = sp_b[q];
        #pragma unroll
        for (int j = 0; j < ATT; j++) a += sp_w[q * ATT + j] * sh[j];
        ssp[q] = 1.0f / (1.0f + expf(-a));
    } else if (t < CIN + COUT + 9 + KNUM) {
        int k = t - CIN - COUT - 9;
        float a = k_b[k];
        #pragma unroll
        for (int j = 0; j < ATT; j++) a += k_w[k * ATT + j] * sh[j];
        sraw[k] = a;
    }
    __syncthreads();
    if (t == 0) {
        float m  = fmaxf(sraw[0], sraw[1]);
        float e0 = expf(sraw[0] - m);
        float e1 = expf(sraw[1] - m);
        float inv = 1.0f / (e0 + e1);
        skk[0] = e0 * inv;
        skk[1] = e1 * inv;
    }
    __syncthreads();

    const int WSZ = COUT * CIN * 9;
    for (int idx = t; idx < WSZ; idx += blockDim.x) {
        int co  = idx / (CIN * 9);
        int rem = idx % (CIN * 9);
        int ci  = rem / 9;
        int q   = rem % 9;
        float w = skk[0] * weight[idx] + skk[1] * weight[WSZ + idx];
        w = w * ssp[q] * sch[ci] * sfs[co];
        g_w[(((size_t)b * 9 + q) * COUT + co) * CIN + ci] = __float2half(w);
    }
    if (b == 0 && t < COUT)
        g_bias[t] = bn_b[t] - bn_m[t] * bn_g[t] * rsqrtf(bn_v[t] + EPS);
}

// ---------------------------------------------------------------------------
// K3: persistent implicit-GEMM conv.
// 296 CTAs (2/SM), each pinned to one b, ~13-14 tiles of (2 rows x 64 cols).
// B (9 taps, 36.9 KB) loaded once per CTA; A double-buffered via cp.async
// (prefetch tile i+1 during compute of tile i). Warp = 32 px x 16 cout x
// K=64 (split-N) -> register-only epilogue, no reduction.
// ---------------------------------------------------------------------------
#define AROWB 8448            // 66 * 128 bytes
#define APART 33792           // 4 * AROWB
#define OFF_B 0               // 9 * 4096 = 36864
#define OFF_A 36864
#define SMEM_TOTAL (OFF_A + 2 * APART)   // 104448
#define NSLOT 37              // 296 / 8 CTAs per sample
#define NTILE 512             // tiles per sample: 128 row-tiles x 4 col-tiles

#define SWZC(byte, r) ((byte) ^ (((r) & 7) << 4))

__device__ __forceinline__ void prefetch_A(u32 sbA, int b, int ty, int tx,
                                           int tid)
{
    const uint4* xh4 = (const uint4*)g_xh;
    for (int i = tid; i < 4 * 8 * 66; i += 256) {
        int row = i / (8 * 66);
        int rem = i % (8 * 66);
        int g   = rem / 66;
        int p   = rem % 66;
        int oy  = ty * 2 - 1 + row;
        int oc  = tx * 64 - 1 + p;
        bool ok = ((unsigned)oy < (unsigned)HO) && ((unsigned)oc < (unsigned)WO);
        const uint4* gp = xh4 +
            ((size_t)(b * 8 + g) * HO + (ok ? oy : 0)) * WO + (ok ? oc : 0);
        u32 sa = sbA + row * AROWB + p * 128 + SWZC(g * 16, p);
        cp16(sa, gp, ok ? 16u : 0u);
    }
}

__global__ void __launch_bounds__(256, 2)
k_conv(float* __restrict__ out)
{
    extern __shared__ char smem[];
    u32 sb = smem_to_u32(smem);
    int tid  = threadIdx.x;
    int w    = tid >> 5;
    int lane = tid & 31;
    int b    = blockIdx.x & 7;
    int slot = blockIdx.x >> 3;          // 0..36

    int nh   = w >> 2;            // cout half (0: co 0-15, 1: co 16-31)
    int pg   = w & 3;             // pixel group
    int wrow = pg >> 1;           // row within tile (0..1)
    int wcol = (pg & 1) * 32;     // col base within 64-tile

    // ---- prologue: B (once) + A(tile0) via cp.async, one group ------------
    for (int i = tid; i < 2304; i += 256) {
        int q    = i / 256;
        int rem2 = i % 256;
        int n    = rem2 >> 3;
        int g    = rem2 & 7;
        const void* gp = (const void*)(g_w +
            (((size_t)b * 9 + q) * COUT + n) * CIN + g * 8);
        cp16(sb + OFF_B + q * 4096 + n * 128 + SWZC(g * 16, n), gp, 16u);
    }
    {
        int lt0 = slot;
        prefetch_A(sb + OFF_A, b, lt0 >> 2, lt0 & 3, tid);
    }
    asm volatile("cp.async.commit_group;" ::: "memory");

    int bufsel = 0;
    for (int lt = slot; lt < NTILE; lt += NSLOT, bufsel ^= 1) {
        int ty = lt >> 2, tx = lt & 3;
        int nlt = lt + NSLOT;
        if (nlt < NTILE) {
            prefetch_A(sb + OFF_A + (bufsel ^ 1) * APART, b,
                       nlt >> 2, nlt & 3, tid);
            asm volatile("cp.async.commit_group;" ::: "memory");
            asm volatile("cp.async.wait_group 1;" ::: "memory");
        } else {
            asm volatile("cp.async.wait_group 0;" ::: "memory");
        }
        __syncthreads();

        // ---- mainloop: 9 taps x 4 k-steps, batched LDSM then MMA ----------
        float acc[2][2][4];
        #pragma unroll
        for (int mt = 0; mt < 2; mt++)
            #pragma unroll
            for (int nt = 0; nt < 2; nt++)
                #pragma unroll
                for (int r = 0; r < 4; r++) acc[mt][nt][r] = 0.0f;

        u32 abase = sb + OFF_A + bufsel * APART;

        #pragma unroll 1
        for (int q = 0; q < 9; q++) {
            int ky = q / 3, kx = q % 3;
            u32 arow  = abase + (wrow + ky) * AROWB;
            u32 bbase = sb + OFF_B + q * 4096;

            u32 bfr[4][2][2];
            u32 afr[4][2][4];
            #pragma unroll
            for (int ks = 0; ks < 4; ks++) {
                int kb = ks * 32;
                #pragma unroll
                for (int nt = 0; nt < 2; nt++) {
                    int n = nh * 16 + nt * 8 + (lane & 7);
                    ldsm_x2(bfr[ks][nt], bbase + n * 128 +
                            SWZC(kb + ((lane >> 3) & 1) * 16, n));
                }
                #pragma unroll
                for (int mt = 0; mt < 2; mt++) {
                    int p = wcol + mt * 16 + (lane & 15) + kx;
                    ldsm_x4(afr[ks][mt], arow + p * 128 +
                            SWZC(kb + ((lane >> 4) ? 16 : 0), p));
                }
            }
            #pragma unroll
            for (int ks = 0; ks < 4; ks++)
                #pragma unroll
                for (int mt = 0; mt < 2; mt++)
                    #pragma unroll
                    for (int nt = 0; nt < 2; nt++)
                        mma_fp16(acc[mt][nt], afr[ks][mt], bfr[ks][nt]);
        }
        __syncthreads();   // all warps done reading this A buffer

        // ---- epilogue (register-only): bias + exact GELU ------------------
        int row = ty * 2 + wrow;
        #pragma unroll
        for (int mt = 0; mt < 2; mt++) {
            int colb = tx * 64 + wcol + mt * 16 + (lane >> 2);
            #pragma unroll
            for (int nt = 0; nt < 2; nt++) {
                int co0 = nh * 16 + nt * 8 + (lane & 3) * 2;
                float b0 = g_bias[co0];
                float b1 = g_bias[co0 + 1];
                #pragma unroll
                for (int r = 0; r < 4; r++) {
                    int co = co0 + (r & 1);
                    int cc = colb + ((r >> 1) ? 8 : 0);
                    float v = acc[mt][nt][r] + ((r & 1) ? b1 : b0);
                    out[(((size_t)b * COUT + co) * HO + row) * WO + cc] =
                        0.5f * v * (1.0f + erff(v * 0.70710678118654752f));
                }
            }
        }
    }
}

// ---------------------------------------------------------------------------
extern "C" void kernel_launch(void* const* d_in, const int* in_sizes, int n_in,
                              void* d_out, int out_size)
{
    const float* x      = (const float*)d_in[0];
    const float* fc_w   = (const float*)d_in[1];
    const float* bna_g  = (const float*)d_in[2];
    const float* bna_b  = (const float*)d_in[3];
    const float* bna_m  = (const float*)d_in[4];
    const float* bna_v  = (const float*)d_in[5];
    const float* ch_w   = (const float*)d_in[6];
    const float* ch_b   = (const float*)d_in[7];
    const float* fil_w  = (const float*)d_in[8];
    const float* fil_b  = (const float*)d_in[9];
    const float* sp_w   = (const float*)d_in[10];
    const float* sp_b   = (const float*)d_in[11];
    const float* k_w    = (const float*)d_in[12];
    const float* k_b    = (const float*)d_in[13];
    const float* weight = (const float*)d_in[14];
    const float* bn_g   = (const float*)d_in[15];
    const float* bn_b   = (const float*)d_in[16];
    const float* bn_m   = (const float*)d_in[17];
    const float* bn_v   = (const float*)d_in[18];

    cudaFuncSetAttribute(k_conv, cudaFuncAttributeMaxDynamicSharedMemorySize,
                         SMEM_TOTAL);

    k_gap<<<B_ * CIN, 256>>>(x);
    k_upsample<<<dim3(HO, 8, B_), 256>>>(x);
    k_attention<<<B_, 256>>>(fc_w, bna_g, bna_b, bna_m, bna_v,
                             ch_w, ch_b, fil_w, fil_b, sp_w, sp_b, k_w, k_b,
                             weight, bn_g, bn_b, bn_m, bn_v);
    k_conv<<<NSLOT * B_, 256, SMEM_TOTAL>>>((float*)d_out);
}